// round 8
// baseline (speedup 1.0000x reference)
#include <cuda_runtime.h>
#include <cuda_bf16.h>
#include <cstdint>

typedef unsigned long long ull;

// ---------------- device-global scratch (no runtime alloc allowed) -------------
// Weight tables, kk-major, gate-interleaved for LDS.128:
//   idx = kk*512 + n*4 + g  ->  float2 {w[g,n,2kk], w[g,n,2kk+1]}   (256KB each)
__device__ float2 g_wsE[64 * 128 * 4];
__device__ float2 g_wsD[64 * 128 * 4];
__device__ ull    g_abE[128 * 4 * 3];      // per (n,gate): {bias,bias},{a0,a0},{a1,a1}
__device__ ull    g_abD[128 * 4 * 3];
__device__ float  g_Wm1T[128 * 256];       // [k][mc]
__device__ float  g_Wm2T[256 * 112];       // [k][mc]

// ---------------- f32x2 + async helpers ----------------------------------------
__device__ __forceinline__ ull f2fma(ull a, ull b, ull c) {
    ull d;
    asm("fma.rn.f32x2 %0, %1, %2, %3;" : "=l"(d) : "l"(a), "l"(b), "l"(c));
    return d;
}
__device__ __forceinline__ ull pk(float lo, float hi) {
    ull r;
    asm("mov.b64 %0, {%1, %2};" : "=l"(r) : "f"(lo), "f"(hi));
    return r;
}
__device__ __forceinline__ float2 unpk(ull v) {
    float2 r;
    asm("mov.b64 {%0, %1}, %2;" : "=f"(r.x), "=f"(r.y) : "l"(v));
    return r;
}
__device__ __forceinline__ void cp_async16(uint32_t saddr, const void* gptr) {
    asm volatile("cp.async.cg.shared.global [%0], [%1], 16;" :: "r"(saddr), "l"(gptr));
}
// HW tanh (MUFU.TANH). sigmoid(x) = 0.5*tanh(x/2) + 0.5
__device__ __forceinline__ float tanha_(float x) {
    float r;
    asm("tanh.approx.f32 %0, %1;" : "=f"(r) : "f"(x));
    return r;
}
__device__ __forceinline__ float sigma_(float x) {
    return fmaf(0.5f, tanha_(0.5f * x), 0.5f);
}

// ---------------- fused precompute kernel --------------------------------------
__global__ void k_prep(const float* __restrict__ Wih_e, const float* __restrict__ We,
                       const float* __restrict__ be,   const float* __restrict__ b_e,
                       const float* __restrict__ Wih_d, const float* __restrict__ Wd,
                       const float* __restrict__ bd,   const float* __restrict__ b_d,
                       const float* __restrict__ Whh_e, const float* __restrict__ Whh_d,
                       const float* __restrict__ Wm1,  const float* __restrict__ Wm2,
                       int E)
{
    int idx0 = blockIdx.x * blockDim.x + threadIdx.x;
    int stride = gridDim.x * blockDim.x;

    // fold A = Wih @ Win (512x2), bias = Wih @ bin + bgate  (encoder + decoder)
    for (int i = idx0; i < 1024; i += stride) {
        int which = i >> 9;          // 0 = enc, 1 = dec
        int gn = i & 511;
        const float* Wih = which ? Wih_d : Wih_e;
        const float* Win = which ? Wd : We;
        const float* bin = which ? bd : be;
        const float* bg  = which ? b_d : b_e;
        ull* ab_out = which ? g_abD : g_abE;
        float a0 = 0.f, a1 = 0.f, bb = 0.f;
        for (int e = 0; e < E; e++) {
            float w = Wih[gn * E + e];
            a0 += w * Win[e * 2 + 0];
            a1 += w * Win[e * 2 + 1];
            bb += w * bin[e];
        }
        bb += bg[gn];
        int n = gn & 127, g = gn >> 7;
        ab_out[(n * 4 + g) * 3 + 0] = pk(bb, bb);
        ab_out[(n * 4 + g) * 3 + 1] = pk(a0, a0);
        ab_out[(n * 4 + g) * 3 + 2] = pk(a1, a1);
    }

    // kk-major gate-interleaved Whh: idx = kk*512 + n*4 + g -> {w(2kk), w(2kk+1)}
    for (int i = idx0; i < 2 * 32768; i += stride) {
        int which = i >= 32768;
        int idx = i & 32767;
        const float* Whh = which ? Whh_d : Whh_e;
        float2* out = which ? g_wsD : g_wsE;
        int g = idx & 3;
        int n = (idx >> 2) & 127;
        int kk = idx >> 9;
        float w0 = Whh[(g * 128 + n) * 128 + 2 * kk + 0];
        float w1 = Whh[(g * 128 + n) * 128 + 2 * kk + 1];
        out[idx] = make_float2(w0, w1);
    }

    // MLP weight transposes
    for (int j = idx0; j < 128 * 256; j += stride) {
        int k = j >> 8, mc = j & 255;
        g_Wm1T[j] = Wm1[mc * 128 + k];
    }
    for (int j = idx0; j < 256 * 112; j += stride) {
        int k = j / 112, mc = j % 112;
        g_Wm2T[j] = Wm2[mc * 256 + k];
    }
}

// ---------------- main persistent kernel ---------------------------------------
// 512 threads, 56 rows (28 pairs) per block. thread: n = tid&127, slot = tid>>7.
// Each slot owns 7 pairs. h, c pair-packed in smem: [pair][k] float2.

#define ROWS  56
#define NPAIR 28
#define JPT   7
#define TMAX  50

// smem layout (bytes):
//  hbuf0 : 0       28672
//  hbuf1 : 28672   28672
//  c_s   : 57344   28672
//  ab_s  : 86016   12288
//  offx  : 98304   11200
//  offy  : 109504  11200
//  base_s: 120704  512     (56 float2)
//  offc  : 121216  512     (x[56], y[56] floats)
//  wr_s  : 121728  1024
//  wstage: 122752  98304   (3 x 32KB weight chunk buffers; m1_s aliases here)
#define WSTAGE_OFF 122752
#define SMEM_BYTES 221056

__device__ __forceinline__ void lstm_step(
    const float2* __restrict__ hin, float2* __restrict__ hout,
    float2* __restrict__ c_s, const ull* __restrict__ ab_s,
    const float2* __restrict__ wd,      // gmem weights, kk-major gate-interleaved
    float2* __restrict__ wstage,        // smem, 3 buffers of 4096 float2
    const ull* __restrict__ offx, const ull* __restrict__ offy,
    int n, int slot, int tid)
{
    ull acc[4][JPT];
    {
        ull bb[4], a0[4], a1[4];
#pragma unroll
        for (int g = 0; g < 4; g++) {
            const ull* q = &ab_s[(n * 4 + g) * 3];
            bb[g] = q[0]; a0[g] = q[1]; a1[g] = q[2];
        }
#pragma unroll
        for (int j = 0; j < JPT; j++) {
            int p = slot * JPT + j;
            ull ox = offx[p], oy = offy[p];
#pragma unroll
            for (int g = 0; g < 4; g++)
                acc[g][j] = f2fma(a0[g], ox, f2fma(a1[g], oy, bb[g]));
        }
    }

    const uint32_t ws_base = (uint32_t)__cvta_generic_to_shared(wstage);

    // prologue: issue chunks 0 and 1 (each 32KB: 2048 x 16B, 4 per thread).
    // Safe: caller guarantees a __syncthreads since the previous step's compute.
#pragma unroll
    for (int c0 = 0; c0 < 2; c0++) {
        const char* src = (const char*)(wd + c0 * 4096) + tid * 16;
        uint32_t dst = ws_base + c0 * 32768 + tid * 16;
#pragma unroll
        for (int k = 0; k < 4; k++)
            cp_async16(dst + k * 8192, src + k * 8192);
        asm volatile("cp.async.commit_group;" ::: "memory");
    }

    const float2* hp = hin + (size_t)slot * JPT * 128;

    int buf = 0;           // buffer index of chunk c (c % 3)
    int nbuf = 2;          // buffer index for chunk c+2
#pragma unroll 1
    for (int c = 0; c < 8; c++) {
        if (c < 7) {
            asm volatile("cp.async.wait_group 1;" ::: "memory");
        } else {
            asm volatile("cp.async.wait_group 0;" ::: "memory");
        }
        __syncthreads();
        // issue chunk c+2 into buffer (c+2)%3 — its last readers (chunk c-1)
        // all passed the barrier above.
        if (c < 6) {
            const char* src = (const char*)(wd + (c + 2) * 4096) + tid * 16;
            uint32_t dst = ws_base + nbuf * 32768 + tid * 16;
#pragma unroll
            for (int k = 0; k < 4; k++)
                cp_async16(dst + k * 8192, src + k * 8192);
            asm volatile("cp.async.commit_group;" ::: "memory");
        }

        const float4* wb4 = (const float4*)(wstage + buf * 4096);
#pragma unroll
        for (int kkl = 0; kkl < 8; kkl++) {
            int kk = c * 8 + kkl;
            // two LDS.128: gates 0,1 and gates 2,3 for this (kk, n)
            float4 wab = wb4[kkl * 256 + 2 * n];
            float4 wcd = wb4[kkl * 256 + 2 * n + 1];
            ull wa[4], wv[4];
            wa[0] = pk(wab.x, wab.x); wv[0] = pk(wab.y, wab.y);
            wa[1] = pk(wab.z, wab.z); wv[1] = pk(wab.w, wab.w);
            wa[2] = pk(wcd.x, wcd.x); wv[2] = pk(wcd.y, wcd.y);
            wa[3] = pk(wcd.z, wcd.z); wv[3] = pk(wcd.w, wcd.w);
#pragma unroll
            for (int j = 0; j < JPT; j++) {
                ulonglong2 hv = *(const ulonglong2*)(hp + j * 128 + 2 * kk);
#pragma unroll
                for (int g = 0; g < 4; g++) {
                    acc[g][j] = f2fma(wa[g], hv.x, acc[g][j]);
                    acc[g][j] = f2fma(wv[g], hv.y, acc[g][j]);
                }
            }
        }
        buf = (buf == 2) ? 0 : buf + 1;
        nbuf = (nbuf == 2) ? 0 : nbuf + 1;
    }

#pragma unroll
    for (int j = 0; j < JPT; j++) {
        int p = slot * JPT + j;
        float2 iv = unpk(acc[0][j]);
        float2 fv = unpk(acc[1][j]);
        float2 gv = unpk(acc[2][j]);
        float2 ov = unpk(acc[3][j]);
        float2 cv = c_s[p * 128 + n];
        float c0 = sigma_(fv.x) * cv.x + sigma_(iv.x) * tanha_(gv.x);
        float c1 = sigma_(fv.y) * cv.y + sigma_(iv.y) * tanha_(gv.y);
        c_s[p * 128 + n] = make_float2(c0, c1);
        hout[p * 128 + n] = make_float2(sigma_(ov.x) * tanha_(c0),
                                        sigma_(ov.y) * tanha_(c1));
    }
}

__global__ void __launch_bounds__(512, 1)
k_main(const float* __restrict__ obs, const float* __restrict__ bm1,
       const float* __restrict__ bm2, const float* __restrict__ Wr,
       const float* __restrict__ br, const float* __restrict__ z,
       float* __restrict__ out, int B, int T, int S)
{
    extern __shared__ char smem[];
    float2* hbuf0 = (float2*)smem;
    float2* hbuf1 = (float2*)(smem + 28672);
    float2* c_s   = (float2*)(smem + 57344);
    ull*    ab_s  = (ull*)(smem + 86016);
    ull*    offx_s = (ull*)(smem + 98304);
    ull*    offy_s = (ull*)(smem + 109504);
    float2* base_s = (float2*)(smem + 120704);
    float*  offc   = (float*)(smem + 121216);   // x[56], y[56]
    float*  wr_s   = (float*)(smem + 121728);   // 256
    float2* wstage = (float2*)(smem + WSTAGE_OFF);
    float2* m1_s   = wstage;                    // aliased: MLP phase only

    const int tid = threadIdx.x;
    const int n = tid & 127;
    const int slot = tid >> 7;
    const int b0 = blockIdx.x * ROWS;
    if (T > TMAX) T = TMAX;

    // ---- init: zero h0/c0, load encoder folded weights, build offsets ----
    for (int i = tid; i < NPAIR * 128; i += 512) {
        hbuf0[i] = make_float2(0.f, 0.f);
        c_s[i] = make_float2(0.f, 0.f);
    }
    for (int i = tid; i < 1536; i += 512) ab_s[i] = g_abE[i];
    if (tid < 256) wr_s[tid] = Wr[tid];

    for (int i = tid; i < ROWS * T; i += 512) {
        int r = i / T, t = i % T;
        int b = b0 + r;
        float ox = 0.f, oy = 0.f;
        float cx = 0.f, cy = 0.f;
        if (b < B) {
            cx = obs[((size_t)b * T + t) * 2 + 0];
            cy = obs[((size_t)b * T + t) * 2 + 1];
            float px = 0.f, py = 0.f;
            if (t > 0) {
                px = obs[((size_t)b * T + t - 1) * 2 + 0];
                py = obs[((size_t)b * T + t - 1) * 2 + 1];
            }
            ox = cx - px; oy = cy - py;
        }
        if (t == T - 1) base_s[r] = make_float2(cx, cy);
        ((float*)&offx_s[t * NPAIR + (r >> 1)])[r & 1] = ox;
        ((float*)&offy_s[t * NPAIR + (r >> 1)])[r & 1] = oy;
    }
    __syncthreads();

    float2* bufs[2] = {hbuf0, hbuf1};
    int par = 0;

    // ---- encoder ----
    for (int t = 0; t < T; t++) {
        lstm_step(bufs[par], bufs[par ^ 1], c_s, ab_s, g_wsE, wstage,
                  &offx_s[t * NPAIR], &offy_s[t * NPAIR], n, slot, tid);
        __syncthreads();
        par ^= 1;
    }

    // ---- save last offsets (decoder init input) + swap to decoder weights ----
    if (tid < NPAIR) {
        ((ull*)offc)[tid]          = offx_s[(T - 1) * NPAIR + tid];
        ((ull*)(offc + ROWS))[tid] = offy_s[(T - 1) * NPAIR + tid];
    }
    for (int i = tid; i < 1536; i += 512) ab_s[i] = g_abD[i];
    __syncthreads();

    // ---- MLP layer 1: m1 = relu(Wm1 @ hF + bm1) (outs n and n+128) ----
    {
        const float2* hf = bufs[par];
        ull acc1[2][JPT];
        float b0f = bm1[n], b1f = bm1[n + 128];
#pragma unroll
        for (int j = 0; j < JPT; j++) { acc1[0][j] = pk(b0f, b0f); acc1[1][j] = pk(b1f, b1f); }
        const float2* hp = hf + (size_t)slot * JPT * 128;
        for (int kk = 0; kk < 64; kk++) {
            float wA0 = g_Wm1T[(2 * kk) * 256 + n];
            float wA1 = g_Wm1T[(2 * kk + 1) * 256 + n];
            float wB0 = g_Wm1T[(2 * kk) * 256 + n + 128];
            float wB1 = g_Wm1T[(2 * kk + 1) * 256 + n + 128];
            ull w00 = pk(wA0, wA0), w01 = pk(wA1, wA1);
            ull w10 = pk(wB0, wB0), w11 = pk(wB1, wB1);
#pragma unroll
            for (int j = 0; j < JPT; j++) {
                ulonglong2 hv = *(const ulonglong2*)(hp + j * 128 + 2 * kk);
                acc1[0][j] = f2fma(w00, hv.x, acc1[0][j]);
                acc1[0][j] = f2fma(w01, hv.y, acc1[0][j]);
                acc1[1][j] = f2fma(w10, hv.x, acc1[1][j]);
                acc1[1][j] = f2fma(w11, hv.y, acc1[1][j]);
            }
        }
        __syncthreads();  // staging region quiesced before m1_s overwrite
#pragma unroll
        for (int j = 0; j < JPT; j++) {
            int p = slot * JPT + j;
            float2 v0 = unpk(acc1[0][j]);
            float2 v1 = unpk(acc1[1][j]);
            m1_s[p * 256 + n]       = make_float2(fmaxf(v0.x, 0.f), fmaxf(v0.y, 0.f));
            m1_s[p * 256 + n + 128] = make_float2(fmaxf(v1.x, 0.f), fmaxf(v1.y, 0.f));
        }
    }
    __syncthreads();

    // ---- MLP layer 2 + concat(z) -> dh written into bufs[par]; reset c ----
    {
        float2* hwr = bufs[par];
        if (n < 112) {
            ull acc2[JPT];
            float bb2 = bm2[n];
#pragma unroll
            for (int j = 0; j < JPT; j++) acc2[j] = pk(bb2, bb2);
            const float2* mp = m1_s + (size_t)slot * JPT * 256;
            for (int kk = 0; kk < 128; kk++) {
                float w0 = g_Wm2T[(2 * kk) * 112 + n];
                float w1 = g_Wm2T[(2 * kk + 1) * 112 + n];
                ull W0 = pk(w0, w0), W1 = pk(w1, w1);
#pragma unroll
                for (int j = 0; j < JPT; j++) {
                    ulonglong2 mv = *(const ulonglong2*)(mp + j * 256 + 2 * kk);
                    acc2[j] = f2fma(W0, mv.x, acc2[j]);
                    acc2[j] = f2fma(W1, mv.y, acc2[j]);
                }
            }
#pragma unroll
            for (int j = 0; j < JPT; j++) {
                int p = slot * JPT + j;
                float2 v = unpk(acc2[j]);
                hwr[p * 128 + n] = make_float2(fmaxf(v.x, 0.f), fmaxf(v.y, 0.f));
            }
        }
        {   // z concat: thread -> (pair, zz)
            int p = tid >> 4, zz = tid & 15;
            if (p < NPAIR) {
                int r0 = b0 + 2 * p, r1 = r0 + 1;
                float z0 = (r0 < B) ? z[(size_t)r0 * 16 + zz] : 0.f;
                float z1 = (r1 < B) ? z[(size_t)r1 * 16 + zz] : 0.f;
                hwr[p * 128 + 112 + zz] = make_float2(z0, z1);
            }
        }
        for (int i = tid; i < NPAIR * 128; i += 512) c_s[i] = make_float2(0.f, 0.f);
    }
    __syncthreads();

    // ---- decoder ----
    const int wwid = tid >> 5, lid = tid & 31;
    const int row_l = 4 * wwid + (lid >> 3);          // 0..63
    const bool row_ok = (row_l < ROWS);
    const int row_c = row_ok ? row_l : 0;
    const int kb = lid & 7;
    const bool rlead = row_ok && ((lid & 7) == 0);
    float2 mybase = base_s[row_c];
    float2 oacc = make_float2(0.f, 0.f);
    float br0 = br[0], br1 = br[1];

    for (int s = 0; s < S; s++) {
        lstm_step(bufs[par], bufs[par ^ 1], c_s, ab_s, g_wsD, wstage,
                  (const ull*)offc, (const ull*)(offc + ROWS), n, slot, tid);
        __syncthreads();
        // readout: off = Wr @ h_new + br ; cumsum output
        const float* hv2 = (const float*)bufs[par ^ 1];
        float p0 = 0.f, p1 = 0.f;
        int bidx = (row_c >> 1) * 256 + (row_c & 1);
#pragma unroll 4
        for (int m = 0; m < 16; m++) {
            int k = kb + 8 * m;
            float hvv = hv2[bidx + 2 * k];
            p0 += wr_s[k] * hvv;
            p1 += wr_s[128 + k] * hvv;
        }
        p0 += __shfl_xor_sync(0xffffffffu, p0, 1);
        p0 += __shfl_xor_sync(0xffffffffu, p0, 2);
        p0 += __shfl_xor_sync(0xffffffffu, p0, 4);
        p1 += __shfl_xor_sync(0xffffffffu, p1, 1);
        p1 += __shfl_xor_sync(0xffffffffu, p1, 2);
        p1 += __shfl_xor_sync(0xffffffffu, p1, 4);
        if (rlead) {
            float ox = p0 + br0, oy = p1 + br1;
            oacc.x += ox; oacc.y += oy;
            offc[row_l] = ox;
            offc[ROWS + row_l] = oy;
            int b = b0 + row_l;
            if (b < B) {
                out[((size_t)b * S + s) * 2 + 0] = mybase.x + oacc.x;
                out[((size_t)b * S + s) * 2 + 1] = mybase.y + oacc.y;
            }
        }
        __syncthreads();
        par ^= 1;
    }
}

// ---------------- launch ------------------------------------------------------
extern "C" void kernel_launch(void* const* d_in, const int* in_sizes, int n_in,
                              void* d_out, int out_size) {
    const float* obs   = (const float*)d_in[0];
    const float* We    = (const float*)d_in[2];
    const float* be    = (const float*)d_in[3];
    const float* Wih_e = (const float*)d_in[4];
    const float* Whh_e = (const float*)d_in[5];
    const float* b_e   = (const float*)d_in[6];
    const float* Wm1   = (const float*)d_in[7];
    const float* bm1   = (const float*)d_in[8];
    const float* Wm2   = (const float*)d_in[9];
    const float* bm2   = (const float*)d_in[10];
    const float* Wd    = (const float*)d_in[11];
    const float* bd    = (const float*)d_in[12];
    const float* Wih_d = (const float*)d_in[13];
    const float* Whh_d = (const float*)d_in[14];
    const float* b_d   = (const float*)d_in[15];
    const float* Wr    = (const float*)d_in[16];
    const float* br    = (const float*)d_in[17];
    const float* z     = (const float*)d_in[18];
    float* out = (float*)d_out;

    int NZ = 16;
    int B = in_sizes[18] / NZ;
    int T = in_sizes[0] / (B * 2);
    int S = out_size / (B * 2);
    int E = in_sizes[2] / 2;

    k_prep<<<256, 256>>>(Wih_e, We, be, b_e, Wih_d, Wd, bd, b_d,
                         Whh_e, Whh_d, Wm1, Wm2, E);

    cudaFuncSetAttribute(k_main, cudaFuncAttributeMaxDynamicSharedMemorySize, SMEM_BYTES);
    int grid = (B + ROWS - 1) / ROWS;
    k_main<<<grid, 512, SMEM_BYTES>>>(obs, bm1, bm2, Wr, br, z, out, B, T, S);
}

// round 9
// speedup vs baseline: 1.1054x; 1.1054x over previous
#include <cuda_runtime.h>
#include <cuda_bf16.h>
#include <cstdint>

typedef unsigned long long ull;

// ---------------- device-global scratch (no runtime alloc allowed) -------------
// Weight tables, kk-major: idx = kk*512 + g*128 + n -> float2 {w(2kk), w(2kk+1)}
// (256KB each; conflict-free LDS.64 per (kk,g) across lanes n)
__device__ float2 g_wsE[64 * 4 * 128];
__device__ float2 g_wsD[64 * 4 * 128];
__device__ ull    g_abE[128 * 4 * 3];      // per (n,gate): {bias,bias},{a0,a0},{a1,a1}
__device__ ull    g_abD[128 * 4 * 3];
__device__ float  g_Wm1T[128 * 256];       // [k][mc]
__device__ float  g_Wm2T[256 * 112];       // [k][mc]

// ---------------- f32x2 + async helpers ----------------------------------------
__device__ __forceinline__ ull f2fma(ull a, ull b, ull c) {
    ull d;
    asm("fma.rn.f32x2 %0, %1, %2, %3;" : "=l"(d) : "l"(a), "l"(b), "l"(c));
    return d;
}
__device__ __forceinline__ ull pk(float lo, float hi) {
    ull r;
    asm("mov.b64 %0, {%1, %2};" : "=l"(r) : "f"(lo), "f"(hi));
    return r;
}
__device__ __forceinline__ float2 unpk(ull v) {
    float2 r;
    asm("mov.b64 {%0, %1}, %2;" : "=f"(r.x), "=f"(r.y) : "l"(v));
    return r;
}
__device__ __forceinline__ void cp_async16(uint32_t saddr, const void* gptr) {
    asm volatile("cp.async.cg.shared.global [%0], [%1], 16;" :: "r"(saddr), "l"(gptr));
}
// HW tanh (MUFU.TANH). sigmoid(x) = 0.5*tanh(x/2) + 0.5
__device__ __forceinline__ float tanha_(float x) {
    float r;
    asm("tanh.approx.f32 %0, %1;" : "=f"(r) : "f"(x));
    return r;
}
__device__ __forceinline__ float sigma_(float x) {
    return fmaf(0.5f, tanha_(0.5f * x), 0.5f);
}

// ---------------- fused precompute kernel --------------------------------------
__global__ void k_prep(const float* __restrict__ Wih_e, const float* __restrict__ We,
                       const float* __restrict__ be,   const float* __restrict__ b_e,
                       const float* __restrict__ Wih_d, const float* __restrict__ Wd,
                       const float* __restrict__ bd,   const float* __restrict__ b_d,
                       const float* __restrict__ Whh_e, const float* __restrict__ Whh_d,
                       const float* __restrict__ Wm1,  const float* __restrict__ Wm2,
                       int E)
{
    int idx0 = blockIdx.x * blockDim.x + threadIdx.x;
    int stride = gridDim.x * blockDim.x;

    // fold A = Wih @ Win (512x2), bias = Wih @ bin + bgate  (encoder + decoder)
    for (int i = idx0; i < 1024; i += stride) {
        int which = i >> 9;          // 0 = enc, 1 = dec
        int gn = i & 511;
        const float* Wih = which ? Wih_d : Wih_e;
        const float* Win = which ? Wd : We;
        const float* bin = which ? bd : be;
        const float* bg  = which ? b_d : b_e;
        ull* ab_out = which ? g_abD : g_abE;
        float a0 = 0.f, a1 = 0.f, bb = 0.f;
        for (int e = 0; e < E; e++) {
            float w = Wih[gn * E + e];
            a0 += w * Win[e * 2 + 0];
            a1 += w * Win[e * 2 + 1];
            bb += w * bin[e];
        }
        bb += bg[gn];
        int n = gn & 127, g = gn >> 7;
        ab_out[(n * 4 + g) * 3 + 0] = pk(bb, bb);
        ab_out[(n * 4 + g) * 3 + 1] = pk(a0, a0);
        ab_out[(n * 4 + g) * 3 + 2] = pk(a1, a1);
    }

    // kk-major Whh layout: idx = kk*512 + g*128 + n  ->  {w(2kk), w(2kk+1)}
    for (int i = idx0; i < 2 * 32768; i += stride) {
        int which = i >= 32768;
        int idx = i & 32767;
        const float* Whh = which ? Whh_d : Whh_e;
        float2* out = which ? g_wsD : g_wsE;
        int n = idx & 127;
        int g = (idx >> 7) & 3;
        int kk = idx >> 9;
        float w0 = Whh[(g * 128 + n) * 128 + 2 * kk + 0];
        float w1 = Whh[(g * 128 + n) * 128 + 2 * kk + 1];
        out[idx] = make_float2(w0, w1);
    }

    // MLP weight transposes
    for (int j = idx0; j < 128 * 256; j += stride) {
        int k = j >> 8, mc = j & 255;
        g_Wm1T[j] = Wm1[mc * 128 + k];
    }
    for (int j = idx0; j < 256 * 112; j += stride) {
        int k = j / 112, mc = j % 112;
        g_Wm2T[j] = Wm2[mc * 256 + k];
    }
}

// ---------------- main persistent kernel ---------------------------------------
// 512 threads, 56 rows (28 pairs) per block. thread: n = tid&127, slot = tid>>7.
// Each slot owns 7 pairs. h, c pair-packed in smem: [pair][k] float2.

#define ROWS  56
#define NPAIR 28
#define JPT   7
#define TMAX  50

// smem layout (bytes):
//  hbuf0 : 0       28672
//  hbuf1 : 28672   28672
//  c_s   : 57344   28672
//  ab_s  : 86016   12288
//  offx  : 98304   11200
//  offy  : 109504  11200
//  base_s: 120704  512     (56 float2)
//  offc  : 121216  512     (x[56], y[56] floats)
//  wr_s  : 121728  1024
//  wstage: 122752  98304   (3 x 32KB weight chunk buffers; m1_s aliases here)
#define WSTAGE_OFF 122752
#define SMEM_BYTES 221056

__device__ __forceinline__ void lstm_step(
    const float2* __restrict__ hin, float2* __restrict__ hout,
    float2* __restrict__ c_s, const ull* __restrict__ ab_s,
    const float2* __restrict__ wd,      // gmem weights, [kk][g][n] float2
    float2* __restrict__ wstage,        // smem, 3 buffers of 4096 float2
    const ull* __restrict__ offx, const ull* __restrict__ offy,
    int n, int slot, int tid)
{
    ull acc[4][JPT];
    {
        ull bb[4], a0[4], a1[4];
#pragma unroll
        for (int g = 0; g < 4; g++) {
            const ull* q = &ab_s[(n * 4 + g) * 3];
            bb[g] = q[0]; a0[g] = q[1]; a1[g] = q[2];
        }
#pragma unroll
        for (int j = 0; j < JPT; j++) {
            int p = slot * JPT + j;
            ull ox = offx[p], oy = offy[p];
#pragma unroll
            for (int g = 0; g < 4; g++)
                acc[g][j] = f2fma(a0[g], ox, f2fma(a1[g], oy, bb[g]));
        }
    }

    const uint32_t ws_base = (uint32_t)__cvta_generic_to_shared(wstage);

    // prologue: issue chunks 0 and 1 (each 32KB: 2048 x 16B, 4 per thread).
    // Safe: caller guarantees a __syncthreads since the previous step's compute.
#pragma unroll
    for (int c0 = 0; c0 < 2; c0++) {
        const char* src = (const char*)(wd + c0 * 4096) + tid * 16;
        uint32_t dst = ws_base + c0 * 32768 + tid * 16;
#pragma unroll
        for (int k = 0; k < 4; k++)
            cp_async16(dst + k * 8192, src + k * 8192);
        asm volatile("cp.async.commit_group;" ::: "memory");
    }

    const float2* hp = hin + (size_t)slot * JPT * 128;

    int buf = 0;           // buffer of chunk c (c % 3)
    int nbuf = 2;          // buffer for chunk c+2
#pragma unroll 1
    for (int c = 0; c < 8; c++) {
        if (c < 7) {
            asm volatile("cp.async.wait_group 1;" ::: "memory");
        } else {
            asm volatile("cp.async.wait_group 0;" ::: "memory");
        }
        __syncthreads();
        // issue chunk c+2 into buffer (c+2)%3 — its last readers (chunk c-1)
        // all passed the barrier above.
        if (c < 6) {
            const char* src = (const char*)(wd + (c + 2) * 4096) + tid * 16;
            uint32_t dst = ws_base + nbuf * 32768 + tid * 16;
#pragma unroll
            for (int k = 0; k < 4; k++)
                cp_async16(dst + k * 8192, src + k * 8192);
            asm volatile("cp.async.commit_group;" ::: "memory");
        }

        const float2* wb = wstage + buf * 4096;
#pragma unroll
        for (int kkl = 0; kkl < 8; kkl++) {
            int kk = c * 8 + kkl;
            // conflict-free LDS.64 per gate: lane stride 8B
            float2 w[4];
#pragma unroll
            for (int g = 0; g < 4; g++)
                w[g] = wb[((kkl * 4 + g) << 7) + n];
            ull wa[4], wv[4];
#pragma unroll
            for (int g = 0; g < 4; g++) {
                wa[g] = pk(w[g].x, w[g].x);
                wv[g] = pk(w[g].y, w[g].y);
            }
#pragma unroll
            for (int j = 0; j < JPT; j++) {
                ulonglong2 hv = *(const ulonglong2*)(hp + j * 128 + 2 * kk);
#pragma unroll
                for (int g = 0; g < 4; g++) {
                    acc[g][j] = f2fma(wa[g], hv.x, acc[g][j]);
                    acc[g][j] = f2fma(wv[g], hv.y, acc[g][j]);
                }
            }
        }
        buf = (buf == 2) ? 0 : buf + 1;
        nbuf = (nbuf == 2) ? 0 : nbuf + 1;
    }

#pragma unroll
    for (int j = 0; j < JPT; j++) {
        int p = slot * JPT + j;
        float2 iv = unpk(acc[0][j]);
        float2 fv = unpk(acc[1][j]);
        float2 gv = unpk(acc[2][j]);
        float2 ov = unpk(acc[3][j]);
        float2 cv = c_s[p * 128 + n];
        float c0 = sigma_(fv.x) * cv.x + sigma_(iv.x) * tanha_(gv.x);
        float c1 = sigma_(fv.y) * cv.y + sigma_(iv.y) * tanha_(gv.y);
        c_s[p * 128 + n] = make_float2(c0, c1);
        hout[p * 128 + n] = make_float2(sigma_(ov.x) * tanha_(c0),
                                        sigma_(ov.y) * tanha_(c1));
    }
}

__global__ void __launch_bounds__(512, 1)
k_main(const float* __restrict__ obs, const float* __restrict__ bm1,
       const float* __restrict__ bm2, const float* __restrict__ Wr,
       const float* __restrict__ br, const float* __restrict__ z,
       float* __restrict__ out, int B, int T, int S)
{
    extern __shared__ char smem[];
    float2* hbuf0 = (float2*)smem;
    float2* hbuf1 = (float2*)(smem + 28672);
    float2* c_s   = (float2*)(smem + 57344);
    ull*    ab_s  = (ull*)(smem + 86016);
    ull*    offx_s = (ull*)(smem + 98304);
    ull*    offy_s = (ull*)(smem + 109504);
    float2* base_s = (float2*)(smem + 120704);
    float*  offc   = (float*)(smem + 121216);   // x[56], y[56]
    float*  wr_s   = (float*)(smem + 121728);   // 256
    float2* wstage = (float2*)(smem + WSTAGE_OFF);
    float2* m1_s   = wstage;                    // aliased: MLP phase only

    const int tid = threadIdx.x;
    const int n = tid & 127;
    const int slot = tid >> 7;
    const int b0 = blockIdx.x * ROWS;
    if (T > TMAX) T = TMAX;

    // ---- init: zero h0/c0, load encoder folded weights, build offsets ----
    for (int i = tid; i < NPAIR * 128; i += 512) {
        hbuf0[i] = make_float2(0.f, 0.f);
        c_s[i] = make_float2(0.f, 0.f);
    }
    for (int i = tid; i < 1536; i += 512) ab_s[i] = g_abE[i];
    if (tid < 256) wr_s[tid] = Wr[tid];

    for (int i = tid; i < ROWS * T; i += 512) {
        int r = i / T, t = i % T;
        int b = b0 + r;
        float ox = 0.f, oy = 0.f;
        float cx = 0.f, cy = 0.f;
        if (b < B) {
            cx = obs[((size_t)b * T + t) * 2 + 0];
            cy = obs[((size_t)b * T + t) * 2 + 1];
            float px = 0.f, py = 0.f;
            if (t > 0) {
                px = obs[((size_t)b * T + t - 1) * 2 + 0];
                py = obs[((size_t)b * T + t - 1) * 2 + 1];
            }
            ox = cx - px; oy = cy - py;
        }
        if (t == T - 1) base_s[r] = make_float2(cx, cy);
        ((float*)&offx_s[t * NPAIR + (r >> 1)])[r & 1] = ox;
        ((float*)&offy_s[t * NPAIR + (r >> 1)])[r & 1] = oy;
    }
    __syncthreads();

    float2* bufs[2] = {hbuf0, hbuf1};
    int par = 0;

    // ---- encoder ----
    for (int t = 0; t < T; t++) {
        lstm_step(bufs[par], bufs[par ^ 1], c_s, ab_s, g_wsE, wstage,
                  &offx_s[t * NPAIR], &offy_s[t * NPAIR], n, slot, tid);
        __syncthreads();
        par ^= 1;
    }

    // ---- save last offsets (decoder init input) + swap to decoder weights ----
    if (tid < NPAIR) {
        ((ull*)offc)[tid]          = offx_s[(T - 1) * NPAIR + tid];
        ((ull*)(offc + ROWS))[tid] = offy_s[(T - 1) * NPAIR + tid];
    }
    for (int i = tid; i < 1536; i += 512) ab_s[i] = g_abD[i];
    __syncthreads();

    // ---- MLP layer 1: m1 = relu(Wm1 @ hF + bm1) (outs n and n+128) ----
    {
        const float2* hf = bufs[par];
        ull acc1[2][JPT];
        float b0f = bm1[n], b1f = bm1[n + 128];
#pragma unroll
        for (int j = 0; j < JPT; j++) { acc1[0][j] = pk(b0f, b0f); acc1[1][j] = pk(b1f, b1f); }
        const float2* hp = hf + (size_t)slot * JPT * 128;
        for (int kk = 0; kk < 64; kk++) {
            float wA0 = g_Wm1T[(2 * kk) * 256 + n];
            float wA1 = g_Wm1T[(2 * kk + 1) * 256 + n];
            float wB0 = g_Wm1T[(2 * kk) * 256 + n + 128];
            float wB1 = g_Wm1T[(2 * kk + 1) * 256 + n + 128];
            ull w00 = pk(wA0, wA0), w01 = pk(wA1, wA1);
            ull w10 = pk(wB0, wB0), w11 = pk(wB1, wB1);
#pragma unroll
            for (int j = 0; j < JPT; j++) {
                ulonglong2 hv = *(const ulonglong2*)(hp + j * 128 + 2 * kk);
                acc1[0][j] = f2fma(w00, hv.x, acc1[0][j]);
                acc1[0][j] = f2fma(w01, hv.y, acc1[0][j]);
                acc1[1][j] = f2fma(w10, hv.x, acc1[1][j]);
                acc1[1][j] = f2fma(w11, hv.y, acc1[1][j]);
            }
        }
        __syncthreads();  // staging region quiesced before m1_s overwrite
#pragma unroll
        for (int j = 0; j < JPT; j++) {
            int p = slot * JPT + j;
            float2 v0 = unpk(acc1[0][j]);
            float2 v1 = unpk(acc1[1][j]);
            m1_s[p * 256 + n]       = make_float2(fmaxf(v0.x, 0.f), fmaxf(v0.y, 0.f));
            m1_s[p * 256 + n + 128] = make_float2(fmaxf(v1.x, 0.f), fmaxf(v1.y, 0.f));
        }
    }
    __syncthreads();

    // ---- MLP layer 2 + concat(z) -> dh written into bufs[par]; reset c ----
    {
        float2* hwr = bufs[par];
        if (n < 112) {
            ull acc2[JPT];
            float bb2 = bm2[n];
#pragma unroll
            for (int j = 0; j < JPT; j++) acc2[j] = pk(bb2, bb2);
            const float2* mp = m1_s + (size_t)slot * JPT * 256;
            for (int kk = 0; kk < 128; kk++) {
                float w0 = g_Wm2T[(2 * kk) * 112 + n];
                float w1 = g_Wm2T[(2 * kk + 1) * 112 + n];
                ull W0 = pk(w0, w0), W1 = pk(w1, w1);
#pragma unroll
                for (int j = 0; j < JPT; j++) {
                    ulonglong2 mv = *(const ulonglong2*)(mp + j * 256 + 2 * kk);
                    acc2[j] = f2fma(W0, mv.x, acc2[j]);
                    acc2[j] = f2fma(W1, mv.y, acc2[j]);
                }
            }
#pragma unroll
            for (int j = 0; j < JPT; j++) {
                int p = slot * JPT + j;
                float2 v = unpk(acc2[j]);
                hwr[p * 128 + n] = make_float2(fmaxf(v.x, 0.f), fmaxf(v.y, 0.f));
            }
        }
        {   // z concat: thread -> (pair, zz)
            int p = tid >> 4, zz = tid & 15;
            if (p < NPAIR) {
                int r0 = b0 + 2 * p, r1 = r0 + 1;
                float z0 = (r0 < B) ? z[(size_t)r0 * 16 + zz] : 0.f;
                float z1 = (r1 < B) ? z[(size_t)r1 * 16 + zz] : 0.f;
                hwr[p * 128 + 112 + zz] = make_float2(z0, z1);
            }
        }
        for (int i = tid; i < NPAIR * 128; i += 512) c_s[i] = make_float2(0.f, 0.f);
    }
    __syncthreads();

    // ---- decoder ----
    const int wwid = tid >> 5, lid = tid & 31;
    const int row_l = 4 * wwid + (lid >> 3);          // 0..63
    const bool row_ok = (row_l < ROWS);
    const int row_c = row_ok ? row_l : 0;
    const int kb = lid & 7;
    const bool rlead = row_ok && ((lid & 7) == 0);
    float2 mybase = base_s[row_c];
    float2 oacc = make_float2(0.f, 0.f);
    float br0 = br[0], br1 = br[1];

    for (int s = 0; s < S; s++) {
        lstm_step(bufs[par], bufs[par ^ 1], c_s, ab_s, g_wsD, wstage,
                  (const ull*)offc, (const ull*)(offc + ROWS), n, slot, tid);
        __syncthreads();
        // readout: off = Wr @ h_new + br ; cumsum output
        const float* hv2 = (const float*)bufs[par ^ 1];
        float p0 = 0.f, p1 = 0.f;
        int bidx = (row_c >> 1) * 256 + (row_c & 1);
#pragma unroll 4
        for (int m = 0; m < 16; m++) {
            int k = kb + 8 * m;
            float hvv = hv2[bidx + 2 * k];
            p0 += wr_s[k] * hvv;
            p1 += wr_s[128 + k] * hvv;
        }
        p0 += __shfl_xor_sync(0xffffffffu, p0, 1);
        p0 += __shfl_xor_sync(0xffffffffu, p0, 2);
        p0 += __shfl_xor_sync(0xffffffffu, p0, 4);
        p1 += __shfl_xor_sync(0xffffffffu, p1, 1);
        p1 += __shfl_xor_sync(0xffffffffu, p1, 2);
        p1 += __shfl_xor_sync(0xffffffffu, p1, 4);
        if (rlead) {
            float ox = p0 + br0, oy = p1 + br1;
            oacc.x += ox; oacc.y += oy;
            offc[row_l] = ox;
            offc[ROWS + row_l] = oy;
            int b = b0 + row_l;
            if (b < B) {
                out[((size_t)b * S + s) * 2 + 0] = mybase.x + oacc.x;
                out[((size_t)b * S + s) * 2 + 1] = mybase.y + oacc.y;
            }
        }
        __syncthreads();
        par ^= 1;
    }
}

// ---------------- launch ------------------------------------------------------
extern "C" void kernel_launch(void* const* d_in, const int* in_sizes, int n_in,
                              void* d_out, int out_size) {
    const float* obs   = (const float*)d_in[0];
    const float* We    = (const float*)d_in[2];
    const float* be    = (const float*)d_in[3];
    const float* Wih_e = (const float*)d_in[4];
    const float* Whh_e = (const float*)d_in[5];
    const float* b_e   = (const float*)d_in[6];
    const float* Wm1   = (const float*)d_in[7];
    const float* bm1   = (const float*)d_in[8];
    const float* Wm2   = (const float*)d_in[9];
    const float* bm2   = (const float*)d_in[10];
    const float* Wd    = (const float*)d_in[11];
    const float* bd    = (const float*)d_in[12];
    const float* Wih_d = (const float*)d_in[13];
    const float* Whh_d = (const float*)d_in[14];
    const float* b_d   = (const float*)d_in[15];
    const float* Wr    = (const float*)d_in[16];
    const float* br    = (const float*)d_in[17];
    const float* z     = (const float*)d_in[18];
    float* out = (float*)d_out;

    int NZ = 16;
    int B = in_sizes[18] / NZ;
    int T = in_sizes[0] / (B * 2);
    int S = out_size / (B * 2);
    int E = in_sizes[2] / 2;

    k_prep<<<256, 256>>>(Wih_e, We, be, b_e, Wih_d, Wd, bd, b_d,
                         Whh_e, Whh_d, Wm1, Wm2, E);

    cudaFuncSetAttribute(k_main, cudaFuncAttributeMaxDynamicSharedMemorySize, SMEM_BYTES);
    int grid = (B + ROWS - 1) / ROWS;
    k_main<<<grid, 512, SMEM_BYTES>>>(obs, bm1, bm2, Wr, br, z, out, B, T, S);
}